// round 1
// baseline (speedup 1.0000x reference)
#include <cuda_runtime.h>
#include <math.h>

// ---------------- problem constants ----------------
#define BATCH   4
#define SLEN    2048
#define NHEAD   16
#define HDIM    64
#define HID     1024
#define ROWS    (BATCH * SLEN)          // 8192
#define NQKV    (3 * HID)               // 3072
#define QSCALE  0.125f                  // 64^-0.5
#define MASKB   (-10000.0f)

// ---------------- scratch (device globals; allocation-free) ----------------
__device__ float g_q[BATCH * NHEAD * SLEN * HDIM];   // [B,H,S,D], pre-scaled
__device__ float g_k[BATCH * NHEAD * SLEN * HDIM];
__device__ float g_v[BATCH * NHEAD * SLEN * HDIM];
__device__ float g_ctx[ROWS * HID];                  // [B,S,H*D]

// ============================================================
// SGEMM: C = A[ROWS,HID] @ W[HID,N] + bias
//   QKV==true : scatter into g_k / g_v / g_q  (chunk order k,v,q)
//   QKV==false: write to out (d_out)
// 128x128 block tile, BK=8, 8x8 per thread, 256 threads
// ============================================================
template<int N, bool QKV>
__global__ void __launch_bounds__(256) sgemm_kernel(const float* __restrict__ A,
                                                    const float* __restrict__ W,
                                                    const float* __restrict__ bias,
                                                    float* __restrict__ out)
{
    __shared__ float As[8][128];
    __shared__ float Bs[8][128];

    const int tid  = threadIdx.x;
    const int row0 = blockIdx.y * 128;
    const int col0 = blockIdx.x * 128;

    const float* Abase = QKV ? A : (const float*)g_ctx;

    const int aRow = tid >> 1;
    const int aCol = (tid & 1) * 4;
    const int bRow = tid >> 5;
    const int bCol = (tid & 31) * 4;

    const float* Aptr = Abase + (row0 + aRow) * HID + aCol;
    const float* Wptr = W + bRow * N + col0 + bCol;

    const int tr = tid >> 4;   // 0..15
    const int tc = tid & 15;   // 0..15

    float acc[8][8];
#pragma unroll
    for (int i = 0; i < 8; i++)
#pragma unroll
        for (int j = 0; j < 8; j++) acc[i][j] = 0.0f;

    for (int k0 = 0; k0 < HID; k0 += 8) {
        float4 av = *(const float4*)(Aptr + k0);
        As[aCol + 0][aRow] = av.x;
        As[aCol + 1][aRow] = av.y;
        As[aCol + 2][aRow] = av.z;
        As[aCol + 3][aRow] = av.w;
        *(float4*)&Bs[bRow][bCol] = *(const float4*)(Wptr + (long)k0 * N);
        __syncthreads();

#pragma unroll
        for (int kk = 0; kk < 8; kk++) {
            float ra[8], rb[8];
#pragma unroll
            for (int i = 0; i < 8; i++) ra[i] = As[kk][tr * 8 + i];
#pragma unroll
            for (int j = 0; j < 8; j++) rb[j] = Bs[kk][tc * 8 + j];
#pragma unroll
            for (int i = 0; i < 8; i++)
#pragma unroll
                for (int j = 0; j < 8; j++)
                    acc[i][j] += ra[i] * rb[j];
        }
        __syncthreads();
    }

    // epilogue
#pragma unroll
    for (int i = 0; i < 8; i++) {
        const int r = row0 + tr * 8 + i;
#pragma unroll
        for (int j = 0; j < 8; j++) {
            const int c = col0 + tc * 8 + j;
            float v = acc[i][j] + bias[c];
            if (QKV) {
                const int chunk = c >> 10;       // 0=k 1=v 2=q
                const int cc    = c & 1023;
                const int h     = cc >> 6;
                const int d     = cc & 63;
                const int b     = r >> 11;       // r / 2048
                const int s     = r & 2047;
                const int idx   = ((b * NHEAD + h) * SLEN + s) * HDIM + d;
                if (chunk == 0)      g_k[idx] = v;
                else if (chunk == 1) g_v[idx] = v;
                else                 g_q[idx] = v * QSCALE;
            } else {
                out[(long)r * HID + c] = v;
            }
        }
    }
}

// ============================================================
// Flash attention (fp32, causal), 64x64 tiles, online softmax.
// grid = (S/64, NHEAD, BATCH), 256 threads (16x16 logical).
// Writes context in [B,S,H*D] layout into g_ctx.
// ============================================================
#define QS_STRIDE 68
#define FLASH_SMEM ((3 * 64 * QS_STRIDE + 64 * 64) * 4)

__device__ __forceinline__ float redmax16(float v) {
    v = fmaxf(v, __shfl_xor_sync(0xffffffffu, v, 8));
    v = fmaxf(v, __shfl_xor_sync(0xffffffffu, v, 4));
    v = fmaxf(v, __shfl_xor_sync(0xffffffffu, v, 2));
    v = fmaxf(v, __shfl_xor_sync(0xffffffffu, v, 1));
    return v;
}
__device__ __forceinline__ float redsum16(float v) {
    v += __shfl_xor_sync(0xffffffffu, v, 8);
    v += __shfl_xor_sync(0xffffffffu, v, 4);
    v += __shfl_xor_sync(0xffffffffu, v, 2);
    v += __shfl_xor_sync(0xffffffffu, v, 1);
    return v;
}

__global__ void __launch_bounds__(256) flash_kernel()
{
    extern __shared__ float sm[];
    float* Qs = sm;                       // 64 x 68
    float* Ks = sm + 64 * QS_STRIDE;      // 64 x 68
    float* Ps = sm + 2 * 64 * QS_STRIDE;  // 64 x 68
    float* Vs = sm + 3 * 64 * QS_STRIDE;  // 64 x 64

    const int tid = threadIdx.x;
    const int ty  = tid >> 4;   // 0..15
    const int tx  = tid & 15;   // 0..15
    const int qt  = blockIdx.x;
    const int h   = blockIdx.y;
    const int b   = blockIdx.z;
    const int q0  = qt * 64;

    const float* Qg = g_q + ((b * NHEAD + h) * SLEN) * HDIM;
    const float* Kg = g_k + ((b * NHEAD + h) * SLEN) * HDIM;
    const float* Vg = g_v + ((b * NHEAD + h) * SLEN) * HDIM;

    // load Q tile: 64 rows x 64 cols
#pragma unroll
    for (int t = 0; t < 4; t++) {
        const int idx = tid + t * 256;       // float4 index, 0..1023
        const int r   = idx >> 4;
        const int c4  = (idx & 15) * 4;
        *(float4*)&Qs[r * QS_STRIDE + c4] = *(const float4*)(Qg + (q0 + r) * HDIM + c4);
    }

    float m[4], l[4], o[4][4];
#pragma unroll
    for (int i = 0; i < 4; i++) {
        m[i] = -1e30f; l[i] = 0.0f;
#pragma unroll
        for (int j = 0; j < 4; j++) o[i][j] = 0.0f;
    }

    for (int t = 0; t <= qt; t++) {
        const int k0 = t * 64;
#pragma unroll
        for (int tt = 0; tt < 4; tt++) {
            const int idx = tid + tt * 256;
            const int r   = idx >> 4;
            const int c4  = (idx & 15) * 4;
            *(float4*)&Ks[r * QS_STRIDE + c4] = *(const float4*)(Kg + (k0 + r) * HDIM + c4);
            *(float4*)&Vs[r * 64 + c4]        = *(const float4*)(Vg + (k0 + r) * HDIM + c4);
        }
        __syncthreads();

        // S = Q @ K^T  (4x4 per thread)
        float s[4][4];
#pragma unroll
        for (int i = 0; i < 4; i++)
#pragma unroll
            for (int j = 0; j < 4; j++) s[i][j] = 0.0f;

#pragma unroll
        for (int k = 0; k < 64; k += 4) {
            float4 a[4], bb[4];
#pragma unroll
            for (int i = 0; i < 4; i++) a[i]  = *(const float4*)&Qs[(ty * 4 + i) * QS_STRIDE + k];
#pragma unroll
            for (int j = 0; j < 4; j++) bb[j] = *(const float4*)&Ks[(tx * 4 + j) * QS_STRIDE + k];
#pragma unroll
            for (int i = 0; i < 4; i++)
#pragma unroll
                for (int j = 0; j < 4; j++)
                    s[i][j] += a[i].x * bb[j].x + a[i].y * bb[j].y
                             + a[i].z * bb[j].z + a[i].w * bb[j].w;
        }

        // causal mask (only the diagonal tile is partially masked)
        if (t == qt) {
#pragma unroll
            for (int i = 0; i < 4; i++) {
                const int qg = q0 + ty * 4 + i;
#pragma unroll
                for (int j = 0; j < 4; j++) {
                    const int kg = k0 + tx * 4 + j;
                    if (kg > qg) s[i][j] = MASKB;
                }
            }
        }

        // online softmax update
#pragma unroll
        for (int i = 0; i < 4; i++) {
            float rmax = fmaxf(fmaxf(s[i][0], s[i][1]), fmaxf(s[i][2], s[i][3]));
            rmax = redmax16(rmax);
            const float mnew = fmaxf(m[i], rmax);
            const float corr = __expf(m[i] - mnew);
            float rs = 0.0f;
#pragma unroll
            for (int j = 0; j < 4; j++) {
                const float p = __expf(s[i][j] - mnew);
                Ps[(ty * 4 + i) * QS_STRIDE + tx * 4 + j] = p;
                rs += p;
            }
            rs = redsum16(rs);
            l[i] = l[i] * corr + rs;
            m[i] = mnew;
#pragma unroll
            for (int j = 0; j < 4; j++) o[i][j] *= corr;
        }
        __syncthreads();

        // O += P @ V
#pragma unroll
        for (int k = 0; k < 64; k += 4) {
            float4 a[4];
#pragma unroll
            for (int i = 0; i < 4; i++) a[i] = *(const float4*)&Ps[(ty * 4 + i) * QS_STRIDE + k];
            const float4 v0 = *(const float4*)&Vs[(k + 0) * 64 + tx * 4];
            const float4 v1 = *(const float4*)&Vs[(k + 1) * 64 + tx * 4];
            const float4 v2 = *(const float4*)&Vs[(k + 2) * 64 + tx * 4];
            const float4 v3 = *(const float4*)&Vs[(k + 3) * 64 + tx * 4];
#pragma unroll
            for (int i = 0; i < 4; i++) {
                o[i][0] += a[i].x * v0.x + a[i].y * v1.x + a[i].z * v2.x + a[i].w * v3.x;
                o[i][1] += a[i].x * v0.y + a[i].y * v1.y + a[i].z * v2.y + a[i].w * v3.y;
                o[i][2] += a[i].x * v0.z + a[i].y * v1.z + a[i].z * v2.z + a[i].w * v3.z;
                o[i][3] += a[i].x * v0.w + a[i].y * v1.w + a[i].z * v2.w + a[i].w * v3.w;
            }
        }
        __syncthreads();
    }

    // normalize + store ctx in [B, S, H*D]
#pragma unroll
    for (int i = 0; i < 4; i++) {
        const float inv = 1.0f / l[i];
        float4 r;
        r.x = o[i][0] * inv; r.y = o[i][1] * inv;
        r.z = o[i][2] * inv; r.w = o[i][3] * inv;
        const int row = b * SLEN + q0 + ty * 4 + i;
        *(float4*)&g_ctx[(long)row * HID + h * HDIM + tx * 4] = r;
    }
}

// ============================================================
// launch
// ============================================================
extern "C" void kernel_launch(void* const* d_in, const int* in_sizes, int n_in,
                              void* d_out, int out_size)
{
    const float* hs      = (const float*)d_in[0];
    const float* w_qkv   = (const float*)d_in[1];
    const float* b_qkv   = (const float*)d_in[2];
    const float* w_dense = (const float*)d_in[3];
    const float* b_dense = (const float*)d_in[4];
    float* out = (float*)d_out;

    cudaFuncSetAttribute(flash_kernel, cudaFuncAttributeMaxDynamicSharedMemorySize, FLASH_SMEM);

    dim3 g1(NQKV / 128, ROWS / 128);   // (24, 64)
    sgemm_kernel<NQKV, true><<<g1, 256>>>(hs, w_qkv, b_qkv, nullptr);

    dim3 g2(SLEN / 64, NHEAD, BATCH);  // (32, 16, 4)
    flash_kernel<<<g2, 256, FLASH_SMEM>>>();

    dim3 g3(HID / 128, ROWS / 128);    // (8, 64)
    sgemm_kernel<HID, false><<<g3, 256>>>(nullptr, w_dense, b_dense, out);
}

// round 3
// speedup vs baseline: 1.4526x; 1.4526x over previous
#include <cuda_runtime.h>
#include <cuda_bf16.h>
#include <cstdint>
#include <math.h>

// ---------------- problem constants ----------------
#define BATCH   4
#define SLEN    2048
#define NHEAD   16
#define HDIM    64
#define HID     1024
#define ROWS    (BATCH * SLEN)          // 8192
#define NQKV    (3 * HID)               // 3072
#define QSCALE  0.125f
#define MASKB   (-10000.0f)

// ---------------- scratch (device globals; allocation-free) ----------------
__device__ __align__(128) float g_q[BATCH * NHEAD * SLEN * HDIM];
__device__ __align__(128) float g_k[BATCH * NHEAD * SLEN * HDIM];
__device__ __align__(128) float g_v[BATCH * NHEAD * SLEN * HDIM];
__device__ __align__(128) float g_ctx[ROWS * HID];

__device__ __align__(128) __nv_bfloat16 g_Ah[ROWS * HID];
__device__ __align__(128) __nv_bfloat16 g_Al[ROWS * HID];
__device__ __align__(128) __nv_bfloat16 g_Ch[ROWS * HID];
__device__ __align__(128) __nv_bfloat16 g_Cl[ROWS * HID];
__device__ __align__(128) __nv_bfloat16 g_Wqh[NQKV * HID];  // w_qkv^T  [N,K]
__device__ __align__(128) __nv_bfloat16 g_Wql[NQKV * HID];
__device__ __align__(128) __nv_bfloat16 g_Wdh[HID * HID];   // w_dense^T [N,K]
__device__ __align__(128) __nv_bfloat16 g_Wdl[HID * HID];

// ============================================================
// PTX helpers (compute_100-safe: cp.async / ldmatrix / mma.sync)
// ============================================================
__device__ __forceinline__ uint32_t smem_u32(const void* p) {
    uint32_t a;
    asm("{ .reg .u64 t; cvta.to.shared.u64 t, %1; cvt.u32.u64 %0, t; }" : "=r"(a) : "l"(p));
    return a;
}
__device__ __forceinline__ void cp16(uint32_t sdst, const void* gsrc) {
    asm volatile("cp.async.ca.shared.global [%0], [%1], 16;" :: "r"(sdst), "l"(gsrc));
}
#define CP_COMMIT() asm volatile("cp.async.commit_group;" ::: "memory")
#define CP_WAIT(n)  asm volatile("cp.async.wait_group %0;" :: "n"(n) : "memory")

__device__ __forceinline__ void ldsm_x4(uint32_t* r, uint32_t addr) {
    asm volatile("ldmatrix.sync.aligned.m8n8.x4.shared.b16 {%0,%1,%2,%3}, [%4];"
        : "=r"(r[0]), "=r"(r[1]), "=r"(r[2]), "=r"(r[3]) : "r"(addr));
}
__device__ __forceinline__ void mma_bf16(float* d, const uint32_t* a, const uint32_t* b) {
    asm volatile("mma.sync.aligned.m16n8k16.row.col.f32.bf16.bf16.f32 "
        "{%0,%1,%2,%3}, {%4,%5,%6,%7}, {%8,%9}, {%0,%1,%2,%3};"
        : "+f"(d[0]), "+f"(d[1]), "+f"(d[2]), "+f"(d[3])
        : "r"(a[0]), "r"(a[1]), "r"(a[2]), "r"(a[3]), "r"(b[0]), "r"(b[1]));
}

// swizzled offset inside a 128x32 bf16 tile (64B rows, 4x16B chunks)
__device__ __forceinline__ uint32_t tswz(int r, int c) {
    return (uint32_t)(r * 64 + ((c ^ ((r >> 1) & 3)) << 4));
}

// ============================================================
// fp32 -> (hi, lo) bf16 split
// ============================================================
__global__ void split_kernel(const float* __restrict__ in, __nv_bfloat16* __restrict__ hi,
                             __nv_bfloat16* __restrict__ lo, int n)
{
    int i = blockIdx.x * blockDim.x + threadIdx.x;
    int stride = gridDim.x * blockDim.x;
    for (; i < n; i += stride) {
        float x = in[i];
        __nv_bfloat16 h = __float2bfloat16(x);
        hi[i] = h;
        lo[i] = __float2bfloat16(x - __bfloat162float(h));
    }
}

// W[K=1024, N] -> W^T hi/lo [N, 1024]
__global__ void tsplit_kernel(const float* __restrict__ in, __nv_bfloat16* __restrict__ hi,
                              __nv_bfloat16* __restrict__ lo, int N)
{
    __shared__ float s[32][33];
    const int n0 = blockIdx.x * 32, k0 = blockIdx.y * 32;
    const int tx = threadIdx.x, ty = threadIdx.y;
#pragma unroll
    for (int i = 0; i < 32; i += 8)
        s[ty + i][tx] = in[(size_t)(k0 + ty + i) * N + n0 + tx];
    __syncthreads();
#pragma unroll
    for (int i = 0; i < 32; i += 8) {
        float x = s[tx][ty + i];
        __nv_bfloat16 h = __float2bfloat16(x);
        size_t o = (size_t)(n0 + ty + i) * HID + k0 + tx;
        hi[o] = h;
        lo[o] = __float2bfloat16(x - __bfloat162float(h));
    }
}

// ============================================================
// HMMA GEMM: C[128x128/CTA] = A[M,1024] @ (B^T[N,1024])^T, bf16x3 split
//   EPI 0: QKV scatter (+bias, q scaled)   EPI 1: dense (+bias) -> out
// smem: 2 stages x 4 tiles(Ah,Al,Bh,Bl) x 8KB = 64KB dynamic
// ============================================================
#define TILE_B8 8192
#define STAGE_B 32768
#define GEMM_SMEM (2 * STAGE_B)

__device__ __forceinline__ void load_stage(uint32_t sb,
    const __nv_bfloat16* __restrict__ Ah, const __nv_bfloat16* __restrict__ Al,
    const __nv_bfloat16* __restrict__ Bh, const __nv_bfloat16* __restrict__ Bl,
    int row0, int col0, int k0, int tid)
{
    const __nv_bfloat16* srcs[4] = { Ah, Al, Bh, Bl };
    const int bases[4] = { row0, row0, col0, col0 };
#pragma unroll
    for (int tI = 0; tI < 4; tI++) {
#pragma unroll
        for (int h = 0; h < 2; h++) {
            const int q = tid + h * 256;        // chunk id 0..511
            const int r = q >> 2, c = q & 3;
            cp16(sb + tI * TILE_B8 + tswz(r, c),
                 srcs[tI] + (size_t)(bases[tI] + r) * HID + k0 + c * 8);
        }
    }
}

template<int EPI>
__global__ void __launch_bounds__(256) gemm_mma(const __nv_bfloat16* __restrict__ Ah,
                                                const __nv_bfloat16* __restrict__ Al,
                                                const __nv_bfloat16* __restrict__ Bh,
                                                const __nv_bfloat16* __restrict__ Bl,
                                                const float* __restrict__ bias,
                                                float* __restrict__ out)
{
    extern __shared__ char sm[];
    const uint32_t smb = smem_u32(sm);
    const int tid  = threadIdx.x;
    const int lane = tid & 31;
    const int wid  = tid >> 5;
    const int wm   = wid >> 1;          // 0..3  -> m base 32*wm
    const int wn   = wid & 1;           // 0..1  -> n base 64*wn
    const int row0 = blockIdx.y * 128;
    const int col0 = blockIdx.x * 128;

    float acc[2][8][4];
#pragma unroll
    for (int i = 0; i < 2; i++)
#pragma unroll
        for (int j = 0; j < 8; j++)
#pragma unroll
            for (int e = 0; e < 4; e++) acc[i][j][e] = 0.0f;

    // ldmatrix lane addressing (within a 128x32 tile)
    const int arow = (lane & 15);             // + wm*32 + mt*16
    const int akch = lane >> 4;               // 0/1
    const int brow = (lane & 7) + ((lane >> 4) << 3);  // + wn*64 + h*32 + nt2*16
    const int bkch = (lane >> 3) & 1;

    // prologue
    load_stage(smb, Ah, Al, Bh, Bl, row0, col0, 0, tid);
    CP_COMMIT();

    for (int ks = 0; ks < 32; ks++) {
        const uint32_t sb = smb + (uint32_t)(ks & 1) * STAGE_B;
        if (ks < 31) {
            load_stage(smb + (uint32_t)((ks + 1) & 1) * STAGE_B,
                       Ah, Al, Bh, Bl, row0, col0, (ks + 1) * 32, tid);
            CP_COMMIT();
            CP_WAIT(1);
        } else {
            CP_WAIT(0);
        }
        __syncthreads();

#pragma unroll
        for (int s = 0; s < 2; s++) {          // two k16 halves of BK=32
            uint32_t afh[2][4], afl[2][4];
#pragma unroll
            for (int mt = 0; mt < 2; mt++) {
                const int r = wm * 32 + mt * 16 + arow;
                const int c = s * 2 + akch;
                ldsm_x4(afh[mt], sb + 0 * TILE_B8 + tswz(r, c));
                ldsm_x4(afl[mt], sb + 1 * TILE_B8 + tswz(r, c));
            }
#pragma unroll
            for (int h = 0; h < 2; h++) {      // n halves of 32
                uint32_t bfh[2][4], bfl[2][4];
#pragma unroll
                for (int nt2 = 0; nt2 < 2; nt2++) {
                    const int r = wn * 64 + h * 32 + nt2 * 16 + brow;
                    const int c = s * 2 + bkch;
                    ldsm_x4(bfh[nt2], sb + 2 * TILE_B8 + tswz(r, c));
                    ldsm_x4(bfl[nt2], sb + 3 * TILE_B8 + tswz(r, c));
                }
#pragma unroll
                for (int mt = 0; mt < 2; mt++)
#pragma unroll
                    for (int n8 = 0; n8 < 4; n8++) {
                        float* d = acc[mt][h * 4 + n8];
                        const uint32_t* ph = &bfh[n8 >> 1][(n8 & 1) * 2];
                        const uint32_t* pl = &bfl[n8 >> 1][(n8 & 1) * 2];
                        mma_bf16(d, afh[mt], ph);
                        mma_bf16(d, afh[mt], pl);
                        mma_bf16(d, afl[mt], ph);
                    }
            }
        }
        __syncthreads();
    }

    // ---------------- epilogue ----------------
    const int gm  = lane >> 2;          // 0..7
    const int gn2 = (lane & 3) * 2;     // 0,2,4,6
#pragma unroll
    for (int mt = 0; mt < 2; mt++) {
#pragma unroll
        for (int j = 0; j < 8; j++) {
            const int col = col0 + wn * 64 + j * 8 + gn2;
            const float b0 = bias[col], b1 = bias[col + 1];
            const int rlo = row0 + wm * 32 + mt * 16 + gm;
            const int rhi = rlo + 8;
            float v00 = acc[mt][j][0] + b0, v01 = acc[mt][j][1] + b1;
            float v10 = acc[mt][j][2] + b0, v11 = acc[mt][j][3] + b1;
            if (EPI == 0) {
                const int chunk = col >> 10;            // uniform per CTA
                const int cc = col & 1023;
                const int hh = cc >> 6;
                const int dd = cc & 63;
                float* dst = (chunk == 0) ? g_k : (chunk == 1) ? g_v : g_q;
                if (chunk == 2) { v00 *= QSCALE; v01 *= QSCALE; v10 *= QSCALE; v11 *= QSCALE; }
                {
                    const int b_ = rlo >> 11, s_ = rlo & 2047;
                    float2* p = (float2*)(dst + ((size_t)(b_ * NHEAD + hh) * SLEN + s_) * HDIM + dd);
                    *p = make_float2(v00, v01);
                }
                {
                    const int b_ = rhi >> 11, s_ = rhi & 2047;
                    float2* p = (float2*)(dst + ((size_t)(b_ * NHEAD + hh) * SLEN + s_) * HDIM + dd);
                    *p = make_float2(v10, v11);
                }
            } else {
                *(float2*)(out + (size_t)rlo * HID + col) = make_float2(v00, v01);
                *(float2*)(out + (size_t)rhi * HID + col) = make_float2(v10, v11);
            }
        }
    }
}

// ============================================================
// Flash attention (fp32, causal) — unchanged
// ============================================================
#define QS_STRIDE 68
#define FLASH_SMEM ((3 * 64 * QS_STRIDE + 64 * 64) * 4)

__device__ __forceinline__ float redmax16(float v) {
    v = fmaxf(v, __shfl_xor_sync(0xffffffffu, v, 8));
    v = fmaxf(v, __shfl_xor_sync(0xffffffffu, v, 4));
    v = fmaxf(v, __shfl_xor_sync(0xffffffffu, v, 2));
    v = fmaxf(v, __shfl_xor_sync(0xffffffffu, v, 1));
    return v;
}
__device__ __forceinline__ float redsum16(float v) {
    v += __shfl_xor_sync(0xffffffffu, v, 8);
    v += __shfl_xor_sync(0xffffffffu, v, 4);
    v += __shfl_xor_sync(0xffffffffu, v, 2);
    v += __shfl_xor_sync(0xffffffffu, v, 1);
    return v;
}

__global__ void __launch_bounds__(256) flash_kernel()
{
    extern __shared__ float smf[];
    float* Qs = smf;
    float* Ks = smf + 64 * QS_STRIDE;
    float* Ps = smf + 2 * 64 * QS_STRIDE;
    float* Vs = smf + 3 * 64 * QS_STRIDE;

    const int tid = threadIdx.x;
    const int ty  = tid >> 4;
    const int tx  = tid & 15;
    const int qt  = blockIdx.x;
    const int h   = blockIdx.y;
    const int b   = blockIdx.z;
    const int q0  = qt * 64;

    const float* Qg = g_q + ((b * NHEAD + h) * SLEN) * HDIM;
    const float* Kg = g_k + ((b * NHEAD + h) * SLEN) * HDIM;
    const float* Vg = g_v + ((b * NHEAD + h) * SLEN) * HDIM;

#pragma unroll
    for (int t = 0; t < 4; t++) {
        const int idx = tid + t * 256;
        const int r   = idx >> 4;
        const int c4  = (idx & 15) * 4;
        *(float4*)&Qs[r * QS_STRIDE + c4] = *(const float4*)(Qg + (q0 + r) * HDIM + c4);
    }

    float m[4], l[4], o[4][4];
#pragma unroll
    for (int i = 0; i < 4; i++) {
        m[i] = -1e30f; l[i] = 0.0f;
#pragma unroll
        for (int j = 0; j < 4; j++) o[i][j] = 0.0f;
    }

    for (int t = 0; t <= qt; t++) {
        const int k0 = t * 64;
#pragma unroll
        for (int tt = 0; tt < 4; tt++) {
            const int idx = tid + tt * 256;
            const int r   = idx >> 4;
            const int c4  = (idx & 15) * 4;
            *(float4*)&Ks[r * QS_STRIDE + c4] = *(const float4*)(Kg + (k0 + r) * HDIM + c4);
            *(float4*)&Vs[r * 64 + c4]        = *(const float4*)(Vg + (k0 + r) * HDIM + c4);
        }
        __syncthreads();

        float s[4][4];
#pragma unroll
        for (int i = 0; i < 4; i++)
#pragma unroll
            for (int j = 0; j < 4; j++) s[i][j] = 0.0f;

#pragma unroll
        for (int k = 0; k < 64; k += 4) {
            float4 a[4], bb[4];
#pragma unroll
            for (int i = 0; i < 4; i++) a[i]  = *(const float4*)&Qs[(ty * 4 + i) * QS_STRIDE + k];
#pragma unroll
            for (int j = 0; j < 4; j++) bb[j] = *(const float4*)&Ks[(tx * 4 + j) * QS_STRIDE + k];
#pragma unroll
            for (int i = 0; i < 4; i++)
#pragma unroll
                for (int j = 0; j < 4; j++)
                    s[i][j] += a[i].x * bb[j].x + a[i].y * bb[j].y
                             + a[i].z * bb[j].z + a[i].w * bb[j].w;
        }

        if (t == qt) {
#pragma unroll
            for (int i = 0; i < 4; i++) {
                const int qg = q0 + ty * 4 + i;
#pragma unroll
                for (int j = 0; j < 4; j++) {
                    const int kg = k0 + tx * 4 + j;
                    if (kg > qg) s[i][j] = MASKB;
                }
            }
        }

#pragma unroll
        for (int i = 0; i < 4; i++) {
            float rmax = fmaxf(fmaxf(s[i][0], s[i][1]), fmaxf(s[i][2], s[i][3]));
            rmax = redmax16(rmax);
            const float mnew = fmaxf(m[i], rmax);
            const float corr = __expf(m[i] - mnew);
            float rs = 0.0f;
#pragma unroll
            for (int j = 0; j < 4; j++) {
                const float p = __expf(s[i][j] - mnew);
                Ps[(ty * 4 + i) * QS_STRIDE + tx * 4 + j] = p;
                rs += p;
            }
            rs = redsum16(rs);
            l[i] = l[i] * corr + rs;
            m[i] = mnew;
#pragma unroll
            for (int j = 0; j < 4; j++) o[i][j] *= corr;
        }
        __syncthreads();

#pragma unroll
        for (int k = 0; k < 64; k += 4) {
            float4 a[4];
#pragma unroll
            for (int i = 0; i < 4; i++) a[i] = *(const float4*)&Ps[(ty * 4 + i) * QS_STRIDE + k];
            const float4 v0 = *(const float4*)&Vs[(k + 0) * 64 + tx * 4];
            const float4 v1 = *(const float4*)&Vs[(k + 1) * 64 + tx * 4];
            const float4 v2 = *(const float4*)&Vs[(k + 2) * 64 + tx * 4];
            const float4 v3 = *(const float4*)&Vs[(k + 3) * 64 + tx * 4];
#pragma unroll
            for (int i = 0; i < 4; i++) {
                o[i][0] += a[i].x * v0.x + a[i].y * v1.x + a[i].z * v2.x + a[i].w * v3.x;
                o[i][1] += a[i].x * v0.y + a[i].y * v1.y + a[i].z * v2.y + a[i].w * v3.y;
                o[i][2] += a[i].x * v0.z + a[i].y * v1.z + a[i].z * v2.z + a[i].w * v3.z;
                o[i][3] += a[i].x * v0.w + a[i].y * v1.w + a[i].z * v2.w + a[i].w * v3.w;
            }
        }
        __syncthreads();
    }

#pragma unroll
    for (int i = 0; i < 4; i++) {
        const float inv = 1.0f / l[i];
        float4 r;
        r.x = o[i][0] * inv; r.y = o[i][1] * inv;
        r.z = o[i][2] * inv; r.w = o[i][3] * inv;
        const int row = b * SLEN + q0 + ty * 4 + i;
        *(float4*)&g_ctx[(size_t)row * HID + h * HDIM + tx * 4] = r;
    }
}

// ============================================================
// launch
// ============================================================
extern "C" void kernel_launch(void* const* d_in, const int* in_sizes, int n_in,
                              void* d_out, int out_size)
{
    const float* hs      = (const float*)d_in[0];
    const float* w_qkv   = (const float*)d_in[1];
    const float* b_qkv   = (const float*)d_in[2];
    const float* w_dense = (const float*)d_in[3];
    const float* b_dense = (const float*)d_in[4];
    float* out = (float*)d_out;

    __nv_bfloat16 *Ah, *Al, *Ch, *Cl, *Wqh, *Wql, *Wdh, *Wdl;
    cudaGetSymbolAddress((void**)&Ah,  g_Ah);
    cudaGetSymbolAddress((void**)&Al,  g_Al);
    cudaGetSymbolAddress((void**)&Ch,  g_Ch);
    cudaGetSymbolAddress((void**)&Cl,  g_Cl);
    cudaGetSymbolAddress((void**)&Wqh, g_Wqh);
    cudaGetSymbolAddress((void**)&Wql, g_Wql);
    cudaGetSymbolAddress((void**)&Wdh, g_Wdh);
    cudaGetSymbolAddress((void**)&Wdl, g_Wdl);
    float* ctx;
    cudaGetSymbolAddress((void**)&ctx, g_ctx);

    cudaFuncSetAttribute(flash_kernel, cudaFuncAttributeMaxDynamicSharedMemorySize, FLASH_SMEM);
    cudaFuncSetAttribute(gemm_mma<0>, cudaFuncAttributeMaxDynamicSharedMemorySize, GEMM_SMEM);
    cudaFuncSetAttribute(gemm_mma<1>, cudaFuncAttributeMaxDynamicSharedMemorySize, GEMM_SMEM);

    // 1. split activations + weights
    split_kernel<<<2048, 256>>>(hs, Ah, Al, ROWS * HID);
    tsplit_kernel<<<dim3(NQKV / 32, HID / 32), dim3(32, 8)>>>(w_qkv, Wqh, Wql, NQKV);
    tsplit_kernel<<<dim3(HID / 32, HID / 32), dim3(32, 8)>>>(w_dense, Wdh, Wdl, HID);

    // 2. QKV GEMM (HMMA) -> g_k / g_v / g_q
    dim3 gq(NQKV / 128, ROWS / 128);   // (24, 64)
    gemm_mma<0><<<gq, 256, GEMM_SMEM>>>(Ah, Al, Wqh, Wql, b_qkv, nullptr);

    // 3. flash attention -> g_ctx
    dim3 gf(SLEN / 64, NHEAD, BATCH);
    flash_kernel<<<gf, 256, FLASH_SMEM>>>();

    // 4. split ctx, dense GEMM -> out
    split_kernel<<<2048, 256>>>(ctx, Ch, Cl, ROWS * HID);
    dim3 gd(HID / 128, ROWS / 128);    // (8, 64)
    gemm_mma<1><<<gd, 256, GEMM_SMEM>>>(Ch, Cl, Wdh, Wdl, b_dense, out);
}

// round 4
// speedup vs baseline: 3.3629x; 2.3151x over previous
#include <cuda_runtime.h>
#include <cuda_bf16.h>
#include <cstdint>
#include <math.h>

// ---------------- problem constants ----------------
#define BATCH   4
#define SLEN    2048
#define NHEAD   16
#define HDIM    64
#define HID     1024
#define ROWS    (BATCH * SLEN)          // 8192
#define NQKV    (3 * HID)               // 3072
#define QSCALE  0.125f
#define MASKB   (-10000.0f)
#define QKV_EL  (BATCH * NHEAD * SLEN * HDIM)   // 8388608

// ---------------- scratch (device globals; allocation-free) ----------------
__device__ __align__(128) __nv_bfloat16 g_qh[QKV_EL], g_ql[QKV_EL];
__device__ __align__(128) __nv_bfloat16 g_kh[QKV_EL], g_kl[QKV_EL];
__device__ __align__(128) __nv_bfloat16 g_vh[QKV_EL], g_vl[QKV_EL];
__device__ __align__(128) __nv_bfloat16 g_Ah[ROWS * HID], g_Al[ROWS * HID];   // hs split
__device__ __align__(128) __nv_bfloat16 g_Ch[ROWS * HID], g_Cl[ROWS * HID];   // ctx split
__device__ __align__(128) __nv_bfloat16 g_Wqh[NQKV * HID], g_Wql[NQKV * HID]; // w_qkv^T
__device__ __align__(128) __nv_bfloat16 g_Wdh[HID * HID],  g_Wdl[HID * HID];  // w_dense^T

// ============================================================
// PTX helpers (compute_100-safe)
// ============================================================
__device__ __forceinline__ uint32_t smem_u32(const void* p) {
    uint32_t a;
    asm("{ .reg .u64 t; cvta.to.shared.u64 t, %1; cvt.u32.u64 %0, t; }" : "=r"(a) : "l"(p));
    return a;
}
__device__ __forceinline__ void cp16(uint32_t sdst, const void* gsrc) {
    asm volatile("cp.async.ca.shared.global [%0], [%1], 16;" :: "r"(sdst), "l"(gsrc));
}
#define CP_COMMIT() asm volatile("cp.async.commit_group;" ::: "memory")
#define CP_WAIT(n)  asm volatile("cp.async.wait_group %0;" :: "n"(n) : "memory")

__device__ __forceinline__ void ldsm_x4(uint32_t* r, uint32_t addr) {
    asm volatile("ldmatrix.sync.aligned.m8n8.x4.shared.b16 {%0,%1,%2,%3}, [%4];"
        : "=r"(r[0]), "=r"(r[1]), "=r"(r[2]), "=r"(r[3]) : "r"(addr));
}
__device__ __forceinline__ void ldsm_x4_t(uint32_t* r, uint32_t addr) {
    asm volatile("ldmatrix.sync.aligned.m8n8.x4.trans.shared.b16 {%0,%1,%2,%3}, [%4];"
        : "=r"(r[0]), "=r"(r[1]), "=r"(r[2]), "=r"(r[3]) : "r"(addr));
}
__device__ __forceinline__ void mma_bf16(float* d, const uint32_t* a, const uint32_t* b) {
    asm volatile("mma.sync.aligned.m16n8k16.row.col.f32.bf16.bf16.f32 "
        "{%0,%1,%2,%3}, {%4,%5,%6,%7}, {%8,%9}, {%0,%1,%2,%3};"
        : "+f"(d[0]), "+f"(d[1]), "+f"(d[2]), "+f"(d[3])
        : "r"(a[0]), "r"(a[1]), "r"(a[2]), "r"(a[3]), "r"(b[0]), "r"(b[1]));
}

// swizzles: 64B-row tiles (GEMM, 32 bf16 cols) and 128B-row tiles (flash, 64 cols)
__device__ __forceinline__ uint32_t tswz(int r, int c)    { return (uint32_t)(r * 64  + ((c ^ ((r >> 1) & 3)) << 4)); }
__device__ __forceinline__ uint32_t tswz128(int r, int c) { return (uint32_t)(r * 128 + ((c ^ (r & 7)) << 4)); }

// truncation hi/lo bf16 pair packers (for P fragments)
__device__ __forceinline__ uint32_t bf16hi_pair(float a, float b) {
    return __byte_perm(__float_as_uint(a), __float_as_uint(b), 0x7632);
}
__device__ __forceinline__ uint32_t bf16lo_pair(float a, float b) {
    float la = a - __uint_as_float(__float_as_uint(a) & 0xFFFF0000u);
    float lb = b - __uint_as_float(__float_as_uint(b) & 0xFFFF0000u);
    uint32_t r;
    asm("cvt.rn.bf16x2.f32 %0, %1, %2;" : "=r"(r) : "f"(lb), "f"(la));
    return r;
}
// round hi/lo split + paired store
__device__ __forceinline__ void split_store2(__nv_bfloat16* Ph, __nv_bfloat16* Pl,
                                             size_t off, float a, float b) {
    __nv_bfloat16 ha = __float2bfloat16(a), hb = __float2bfloat16(b);
    *(__nv_bfloat162*)(Ph + off) = __halves2bfloat162(ha, hb);
    *(__nv_bfloat162*)(Pl + off) = __halves2bfloat162(
        __float2bfloat16(a - __bfloat162float(ha)),
        __float2bfloat16(b - __bfloat162float(hb)));
}

// ============================================================
// fp32 -> (hi, lo) bf16 split
// ============================================================
__global__ void split_kernel(const float* __restrict__ in, __nv_bfloat16* __restrict__ hi,
                             __nv_bfloat16* __restrict__ lo, int n)
{
    int i = blockIdx.x * blockDim.x + threadIdx.x;
    int stride = gridDim.x * blockDim.x;
    for (; i < n; i += stride) {
        float x = in[i];
        __nv_bfloat16 h = __float2bfloat16(x);
        hi[i] = h;
        lo[i] = __float2bfloat16(x - __bfloat162float(h));
    }
}

// W[K=1024, N] -> W^T hi/lo [N, 1024]
__global__ void tsplit_kernel(const float* __restrict__ in, __nv_bfloat16* __restrict__ hi,
                              __nv_bfloat16* __restrict__ lo, int N)
{
    __shared__ float s[32][33];
    const int n0 = blockIdx.x * 32, k0 = blockIdx.y * 32;
    const int tx = threadIdx.x, ty = threadIdx.y;
#pragma unroll
    for (int i = 0; i < 32; i += 8)
        s[ty + i][tx] = in[(size_t)(k0 + ty + i) * N + n0 + tx];
    __syncthreads();
#pragma unroll
    for (int i = 0; i < 32; i += 8) {
        float x = s[tx][ty + i];
        __nv_bfloat16 h = __float2bfloat16(x);
        size_t o = (size_t)(n0 + ty + i) * HID + k0 + tx;
        hi[o] = h;
        lo[o] = __float2bfloat16(x - __bfloat162float(h));
    }
}

// ============================================================
// HMMA GEMM (bf16x3 split): C = A[M,1024] @ (B^T[N,1024])^T
//   EPI 0: QKV -> bf16 hi/lo scatter into q/k/v (q scaled)
//   EPI 1: dense (+bias) -> fp32 out
// ============================================================
#define TILE_B8 8192
#define STAGE_B 32768
#define GEMM_SMEM (2 * STAGE_B)

__device__ __forceinline__ void load_stage(uint32_t sb,
    const __nv_bfloat16* __restrict__ Ah, const __nv_bfloat16* __restrict__ Al,
    const __nv_bfloat16* __restrict__ Bh, const __nv_bfloat16* __restrict__ Bl,
    int row0, int col0, int k0, int tid)
{
    const __nv_bfloat16* srcs[4] = { Ah, Al, Bh, Bl };
    const int bases[4] = { row0, row0, col0, col0 };
#pragma unroll
    for (int tI = 0; tI < 4; tI++) {
#pragma unroll
        for (int h = 0; h < 2; h++) {
            const int q = tid + h * 256;
            const int r = q >> 2, c = q & 3;
            cp16(sb + tI * TILE_B8 + tswz(r, c),
                 srcs[tI] + (size_t)(bases[tI] + r) * HID + k0 + c * 8);
        }
    }
}

template<int EPI>
__global__ void __launch_bounds__(256) gemm_mma(const __nv_bfloat16* __restrict__ Ah,
                                                const __nv_bfloat16* __restrict__ Al,
                                                const __nv_bfloat16* __restrict__ Bh,
                                                const __nv_bfloat16* __restrict__ Bl,
                                                const float* __restrict__ bias,
                                                float* __restrict__ out)
{
    extern __shared__ char sm[];
    const uint32_t smb = smem_u32(sm);
    const int tid  = threadIdx.x;
    const int lane = tid & 31;
    const int wid  = tid >> 5;
    const int wm   = wid >> 1;
    const int wn   = wid & 1;
    const int row0 = blockIdx.y * 128;
    const int col0 = blockIdx.x * 128;

    float acc[2][8][4];
#pragma unroll
    for (int i = 0; i < 2; i++)
#pragma unroll
        for (int j = 0; j < 8; j++)
#pragma unroll
            for (int e = 0; e < 4; e++) acc[i][j][e] = 0.0f;

    const int arow = (lane & 15);
    const int akch = lane >> 4;
    const int brow = (lane & 7) + ((lane >> 4) << 3);
    const int bkch = (lane >> 3) & 1;

    load_stage(smb, Ah, Al, Bh, Bl, row0, col0, 0, tid);
    CP_COMMIT();

    for (int ks = 0; ks < 32; ks++) {
        const uint32_t sb = smb + (uint32_t)(ks & 1) * STAGE_B;
        if (ks < 31) {
            load_stage(smb + (uint32_t)((ks + 1) & 1) * STAGE_B,
                       Ah, Al, Bh, Bl, row0, col0, (ks + 1) * 32, tid);
            CP_COMMIT();
            CP_WAIT(1);
        } else {
            CP_WAIT(0);
        }
        __syncthreads();

#pragma unroll
        for (int s = 0; s < 2; s++) {
            uint32_t afh[2][4], afl[2][4];
#pragma unroll
            for (int mt = 0; mt < 2; mt++) {
                const int r = wm * 32 + mt * 16 + arow;
                const int c = s * 2 + akch;
                ldsm_x4(afh[mt], sb + 0 * TILE_B8 + tswz(r, c));
                ldsm_x4(afl[mt], sb + 1 * TILE_B8 + tswz(r, c));
            }
#pragma unroll
            for (int h = 0; h < 2; h++) {
                uint32_t bfh[2][4], bfl[2][4];
#pragma unroll
                for (int nt2 = 0; nt2 < 2; nt2++) {
                    const int r = wn * 64 + h * 32 + nt2 * 16 + brow;
                    const int c = s * 2 + bkch;
                    ldsm_x4(bfh[nt2], sb + 2 * TILE_B8 + tswz(r, c));
                    ldsm_x4(bfl[nt2], sb + 3 * TILE_B8 + tswz(r, c));
                }
#pragma unroll
                for (int mt = 0; mt < 2; mt++)
#pragma unroll
                    for (int n8 = 0; n8 < 4; n8++) {
                        float* d = acc[mt][h * 4 + n8];
                        const uint32_t* ph = &bfh[n8 >> 1][(n8 & 1) * 2];
                        const uint32_t* pl = &bfl[n8 >> 1][(n8 & 1) * 2];
                        mma_bf16(d, afh[mt], ph);
                        mma_bf16(d, afh[mt], pl);
                        mma_bf16(d, afl[mt], ph);
                    }
            }
        }
        __syncthreads();
    }

    // epilogue
    const int gm  = lane >> 2;
    const int gn2 = (lane & 3) * 2;
#pragma unroll
    for (int mt = 0; mt < 2; mt++) {
#pragma unroll
        for (int j = 0; j < 8; j++) {
            const int col = col0 + wn * 64 + j * 8 + gn2;
            const float b0 = bias[col], b1 = bias[col + 1];
            const int rlo = row0 + wm * 32 + mt * 16 + gm;
            const int rhi = rlo + 8;
            float v00 = acc[mt][j][0] + b0, v01 = acc[mt][j][1] + b1;
            float v10 = acc[mt][j][2] + b0, v11 = acc[mt][j][3] + b1;
            if (EPI == 0) {
                const int chunk = col >> 10;
                const int cc = col & 1023;
                const int hh = cc >> 6;
                const int dd = cc & 63;
                __nv_bfloat16 *dh, *dl;
                if (chunk == 0)      { dh = g_kh; dl = g_kl; }
                else if (chunk == 1) { dh = g_vh; dl = g_vl; }
                else { dh = g_qh; dl = g_ql;
                       v00 *= QSCALE; v01 *= QSCALE; v10 *= QSCALE; v11 *= QSCALE; }
                {
                    const int b_ = rlo >> 11, s_ = rlo & 2047;
                    split_store2(dh, dl, ((size_t)(b_ * NHEAD + hh) * SLEN + s_) * HDIM + dd, v00, v01);
                }
                {
                    const int b_ = rhi >> 11, s_ = rhi & 2047;
                    split_store2(dh, dl, ((size_t)(b_ * NHEAD + hh) * SLEN + s_) * HDIM + dd, v10, v11);
                }
            } else {
                *(float2*)(out + (size_t)rlo * HID + col) = make_float2(v00, v01);
                *(float2*)(out + (size_t)rhi * HID + col) = make_float2(v10, v11);
            }
        }
    }
}

// ============================================================
// Flash attention, HMMA bf16x3, causal. BQ=128, BK=64.
// grid = (16, NHEAD, BATCH), 256 threads (8 warps x 16 q-rows)
// smem: Qh|Ql (32KB) + 2 stages x (Kh|Kl|Vh|Vl) (64KB) = 96KB
// ============================================================
#define FSM_STAGE 32768
#define FLASH_SMEM 98304

__device__ __forceinline__ void load_kv_stage(uint32_t sb,
    const __nv_bfloat16* __restrict__ Kh, const __nv_bfloat16* __restrict__ Kl,
    const __nv_bfloat16* __restrict__ Vh, const __nv_bfloat16* __restrict__ Vl,
    int k0, int tid)
{
    const __nv_bfloat16* srcs[4] = { Kh, Kl, Vh, Vl };
#pragma unroll
    for (int t = 0; t < 4; t++) {
#pragma unroll
        for (int hh = 0; hh < 2; hh++) {
            const int r = (tid >> 3) + hh * 32;
            const int c = tid & 7;
            cp16(sb + t * 8192 + tswz128(r, c), srcs[t] + (size_t)(k0 + r) * HDIM + c * 8);
        }
    }
}

__global__ void __launch_bounds__(256) flash_mma()
{
    extern __shared__ char sm[];
    const uint32_t smb = smem_u32(sm);
    const int tid = threadIdx.x, lane = tid & 31, wid = tid >> 5;
    const int qt = blockIdx.x, h = blockIdx.y, b = blockIdx.z;
    const int q0 = qt * 128;
    const size_t bh = ((size_t)(b * NHEAD + h)) * SLEN * HDIM;
    const __nv_bfloat16 *Qh = g_qh + bh, *Ql = g_ql + bh;
    const __nv_bfloat16 *Kh = g_kh + bh, *Kl = g_kl + bh;
    const __nv_bfloat16 *Vh = g_vh + bh, *Vl = g_vl + bh;
    const int nk = 2 * qt + 2;

    // prologue: Q + stage0 (group A), stage1 (group B)
#pragma unroll
    for (int t = 0; t < 2; t++) {
#pragma unroll
        for (int hh = 0; hh < 4; hh++) {
            const int r = (tid >> 3) + hh * 32;
            const int c = tid & 7;
            cp16(smb + t * 16384 + tswz128(r, c),
                 (t ? Ql : Qh) + (size_t)(q0 + r) * HDIM + c * 8);
        }
    }
    load_kv_stage(smb + FSM_STAGE, Kh, Kl, Vh, Vl, 0, tid);
    CP_COMMIT();
    load_kv_stage(smb + FSM_STAGE + 32768, Kh, Kl, Vh, Vl, 64, tid);
    CP_COMMIT();
    CP_WAIT(1);
    __syncthreads();

    // Q fragments, register-resident
    uint32_t qfh[4][4], qfl[4][4];
    {
        const int arow = 16 * wid + (lane & 15);
        const int ach  = lane >> 4;
#pragma unroll
        for (int s = 0; s < 4; s++) {
            ldsm_x4(qfh[s], smb + tswz128(arow, s * 2 + ach));
            ldsm_x4(qfl[s], smb + 16384 + tswz128(arow, s * 2 + ach));
        }
    }

    float O[8][4];
#pragma unroll
    for (int j = 0; j < 8; j++)
#pragma unroll
        for (int e = 0; e < 4; e++) O[j][e] = 0.0f;
    float m0 = -1e30f, m1 = -1e30f, l0 = 0.0f, l1 = 0.0f;

    const int brow = (lane & 7) + ((lane >> 4) << 3);
    const int bkch = (lane >> 3) & 1;
    const int vrow = lane & 15;
    const int vch  = lane >> 4;
    const int rg0  = q0 + 16 * wid + (lane >> 2);

    for (int t = 0; t < nk; t++) {
        const uint32_t sb = smb + FSM_STAGE + (uint32_t)(t & 1) * 32768;
        const int k0 = t * 64;

        // ---- S = Q K^T (3-term) ----
        float s_[8][4];
#pragma unroll
        for (int j = 0; j < 8; j++)
#pragma unroll
            for (int e = 0; e < 4; e++) s_[j][e] = 0.0f;

#pragma unroll
        for (int s = 0; s < 4; s++) {
#pragma unroll
            for (int jj = 0; jj < 4; jj++) {
                uint32_t kfh[4], kfl[4];
                ldsm_x4(kfh, sb + tswz128(jj * 16 + brow, s * 2 + bkch));
                ldsm_x4(kfl, sb + 8192 + tswz128(jj * 16 + brow, s * 2 + bkch));
                mma_bf16(s_[2 * jj],     qfh[s], kfh + 0);
                mma_bf16(s_[2 * jj],     qfh[s], kfl + 0);
                mma_bf16(s_[2 * jj],     qfl[s], kfh + 0);
                mma_bf16(s_[2 * jj + 1], qfh[s], kfh + 2);
                mma_bf16(s_[2 * jj + 1], qfh[s], kfl + 2);
                mma_bf16(s_[2 * jj + 1], qfl[s], kfh + 2);
            }
        }

        // ---- causal mask (diagonal region only) ----
        if (k0 + 63 > q0 + 16 * wid) {
#pragma unroll
            for (int j = 0; j < 8; j++) {
                const int col = k0 + j * 8 + 2 * (lane & 3);
                if (col     > rg0)     s_[j][0] = MASKB;
                if (col + 1 > rg0)     s_[j][1] = MASKB;
                if (col     > rg0 + 8) s_[j][2] = MASKB;
                if (col + 1 > rg0 + 8) s_[j][3] = MASKB;
            }
        }

        // ---- online softmax ----
        float mx0 = s_[0][0], mx1 = s_[0][2];
#pragma unroll
        for (int j = 0; j < 8; j++) {
            mx0 = fmaxf(mx0, fmaxf(s_[j][0], s_[j][1]));
            mx1 = fmaxf(mx1, fmaxf(s_[j][2], s_[j][3]));
        }
        mx0 = fmaxf(mx0, __shfl_xor_sync(0xffffffffu, mx0, 1));
        mx0 = fmaxf(mx0, __shfl_xor_sync(0xffffffffu, mx0, 2));
        mx1 = fmaxf(mx1, __shfl_xor_sync(0xffffffffu, mx1, 1));
        mx1 = fmaxf(mx1, __shfl_xor_sync(0xffffffffu, mx1, 2));
        const float mn0 = fmaxf(m0, mx0), mn1 = fmaxf(m1, mx1);
        const float c0 = __expf(m0 - mn0), c1 = __expf(m1 - mn1);
        m0 = mn0; m1 = mn1;
        float rs0 = 0.0f, rs1 = 0.0f;
#pragma unroll
        for (int j = 0; j < 8; j++) {
            s_[j][0] = __expf(s_[j][0] - mn0);
            s_[j][1] = __expf(s_[j][1] - mn0);
            s_[j][2] = __expf(s_[j][2] - mn1);
            s_[j][3] = __expf(s_[j][3] - mn1);
            rs0 += s_[j][0] + s_[j][1];
            rs1 += s_[j][2] + s_[j][3];
            O[j][0] *= c0; O[j][1] *= c0; O[j][2] *= c1; O[j][3] *= c1;
        }
        rs0 += __shfl_xor_sync(0xffffffffu, rs0, 1);
        rs0 += __shfl_xor_sync(0xffffffffu, rs0, 2);
        rs1 += __shfl_xor_sync(0xffffffffu, rs1, 1);
        rs1 += __shfl_xor_sync(0xffffffffu, rs1, 2);
        l0 = l0 * c0 + rs0;
        l1 = l1 * c1 + rs1;

        // ---- P fragments (truncation hi/lo split) ----
        uint32_t pah[4][4], pal[4][4];
#pragma unroll
        for (int kk = 0; kk < 4; kk++) {
            const int j0 = 2 * kk, j1 = 2 * kk + 1;
            pah[kk][0] = bf16hi_pair(s_[j0][0], s_[j0][1]);
            pah[kk][1] = bf16hi_pair(s_[j0][2], s_[j0][3]);
            pah[kk][2] = bf16hi_pair(s_[j1][0], s_[j1][1]);
            pah[kk][3] = bf16hi_pair(s_[j1][2], s_[j1][3]);
            pal[kk][0] = bf16lo_pair(s_[j0][0], s_[j0][1]);
            pal[kk][1] = bf16lo_pair(s_[j0][2], s_[j0][3]);
            pal[kk][2] = bf16lo_pair(s_[j1][0], s_[j1][1]);
            pal[kk][3] = bf16lo_pair(s_[j1][2], s_[j1][3]);
        }

        // ---- O += P V (3-term) ----
#pragma unroll
        for (int kk = 0; kk < 4; kk++) {
#pragma unroll
            for (int dd = 0; dd < 4; dd++) {
                uint32_t vfh[4], vfl[4];
                ldsm_x4_t(vfh, sb + 16384 + tswz128(kk * 16 + vrow, 2 * dd + vch));
                ldsm_x4_t(vfl, sb + 24576 + tswz128(kk * 16 + vrow, 2 * dd + vch));
                mma_bf16(O[2 * dd],     pah[kk], vfh + 0);
                mma_bf16(O[2 * dd],     pah[kk], vfl + 0);
                mma_bf16(O[2 * dd],     pal[kk], vfh + 0);
                mma_bf16(O[2 * dd + 1], pah[kk], vfh + 2);
                mma_bf16(O[2 * dd + 1], pah[kk], vfl + 2);
                mma_bf16(O[2 * dd + 1], pal[kk], vfh + 2);
            }
        }

        __syncthreads();
        if (t + 2 < nk) {
            load_kv_stage(smb + FSM_STAGE + (uint32_t)(t & 1) * 32768,
                          Kh, Kl, Vh, Vl, (t + 2) * 64, tid);
            CP_COMMIT();
        }
        if (t + 1 < nk) {
            if (t + 2 < nk) { CP_WAIT(1); } else { CP_WAIT(0); }
            __syncthreads();
        }
    }

    // ---- write ctx hi/lo ----
    const float inv0 = 1.0f / l0, inv1 = 1.0f / l1;
    const int r0 = q0 + 16 * wid + (lane >> 2);
    const int r1 = r0 + 8;
    const size_t base0 = ((size_t)b * SLEN + r0) * HID + h * HDIM + 2 * (lane & 3);
    const size_t base1 = ((size_t)b * SLEN + r1) * HID + h * HDIM + 2 * (lane & 3);
#pragma unroll
    for (int j = 0; j < 8; j++) {
        split_store2(g_Ch, g_Cl, base0 + j * 8, O[j][0] * inv0, O[j][1] * inv0);
        split_store2(g_Ch, g_Cl, base1 + j * 8, O[j][2] * inv1, O[j][3] * inv1);
    }
}

// ============================================================
// launch
// ============================================================
extern "C" void kernel_launch(void* const* d_in, const int* in_sizes, int n_in,
                              void* d_out, int out_size)
{
    const float* hs      = (const float*)d_in[0];
    const float* w_qkv   = (const float*)d_in[1];
    const float* b_qkv   = (const float*)d_in[2];
    const float* w_dense = (const float*)d_in[3];
    const float* b_dense = (const float*)d_in[4];
    float* out = (float*)d_out;

    __nv_bfloat16 *Ah, *Al, *Ch, *Cl, *Wqh, *Wql, *Wdh, *Wdl;
    cudaGetSymbolAddress((void**)&Ah,  g_Ah);
    cudaGetSymbolAddress((void**)&Al,  g_Al);
    cudaGetSymbolAddress((void**)&Ch,  g_Ch);
    cudaGetSymbolAddress((void**)&Cl,  g_Cl);
    cudaGetSymbolAddress((void**)&Wqh, g_Wqh);
    cudaGetSymbolAddress((void**)&Wql, g_Wql);
    cudaGetSymbolAddress((void**)&Wdh, g_Wdh);
    cudaGetSymbolAddress((void**)&Wdl, g_Wdl);

    cudaFuncSetAttribute(flash_mma, cudaFuncAttributeMaxDynamicSharedMemorySize, FLASH_SMEM);
    cudaFuncSetAttribute(gemm_mma<0>, cudaFuncAttributeMaxDynamicSharedMemorySize, GEMM_SMEM);
    cudaFuncSetAttribute(gemm_mma<1>, cudaFuncAttributeMaxDynamicSharedMemorySize, GEMM_SMEM);

    // 1. split inputs
    split_kernel<<<2048, 256>>>(hs, Ah, Al, ROWS * HID);
    tsplit_kernel<<<dim3(NQKV / 32, HID / 32), dim3(32, 8)>>>(w_qkv, Wqh, Wql, NQKV);
    tsplit_kernel<<<dim3(HID / 32, HID / 32), dim3(32, 8)>>>(w_dense, Wdh, Wdl, HID);

    // 2. QKV GEMM -> bf16 hi/lo q/k/v
    dim3 gq(NQKV / 128, ROWS / 128);
    gemm_mma<0><<<gq, 256, GEMM_SMEM>>>(Ah, Al, Wqh, Wql, b_qkv, nullptr);

    // 3. flash attention (HMMA) -> ctx hi/lo
    dim3 gf(SLEN / 128, NHEAD, BATCH);
    flash_mma<<<gf, 256, FLASH_SMEM>>>();

    // 4. dense GEMM -> out
    dim3 gd(HID / 128, ROWS / 128);
    gemm_mma<1><<<gd, 256, GEMM_SMEM>>>(Ch, Cl, Wdh, Wdl, b_dense, out);
}

// round 5
// speedup vs baseline: 3.7075x; 1.1025x over previous
#include <cuda_runtime.h>
#include <cuda_bf16.h>
#include <cstdint>
#include <math.h>

// ---------------- problem constants ----------------
#define BATCH   4
#define SLEN    2048
#define NHEAD   16
#define HDIM    64
#define HID     1024
#define ROWS    (BATCH * SLEN)          // 8192
#define NQKV    (3 * HID)               // 3072
#define QSCALE  0.125f
#define MASKB   (-10000.0f)
#define QKV_EL  (BATCH * NHEAD * SLEN * HDIM)   // 8388608

// ---------------- scratch (device globals; allocation-free) ----------------
__device__ __align__(128) __nv_bfloat16 g_qh[QKV_EL], g_ql[QKV_EL];
__device__ __align__(128) __nv_bfloat16 g_kh[QKV_EL], g_kl[QKV_EL];
__device__ __align__(128) __nv_bfloat16 g_vh[QKV_EL], g_vl[QKV_EL];
__device__ __align__(128) __nv_bfloat16 g_Ah[ROWS * HID], g_Al[ROWS * HID];   // hs split
__device__ __align__(128) __nv_bfloat16 g_Ch[ROWS * HID], g_Cl[ROWS * HID];   // ctx split
__device__ __align__(128) __nv_bfloat16 g_Wqh[NQKV * HID], g_Wql[NQKV * HID]; // w_qkv^T
__device__ __align__(128) __nv_bfloat16 g_Wdh[HID * HID],  g_Wdl[HID * HID];  // w_dense^T

// ============================================================
// PTX helpers (compute_100-safe)
// ============================================================
__device__ __forceinline__ uint32_t smem_u32(const void* p) {
    uint32_t a;
    asm("{ .reg .u64 t; cvta.to.shared.u64 t, %1; cvt.u32.u64 %0, t; }" : "=r"(a) : "l"(p));
    return a;
}
__device__ __forceinline__ void cp16(uint32_t sdst, const void* gsrc) {
    asm volatile("cp.async.ca.shared.global [%0], [%1], 16;" :: "r"(sdst), "l"(gsrc));
}
#define CP_COMMIT() asm volatile("cp.async.commit_group;" ::: "memory")
#define CP_WAIT(n)  asm volatile("cp.async.wait_group %0;" :: "n"(n) : "memory")

__device__ __forceinline__ void ldsm_x4(uint32_t* r, uint32_t addr) {
    asm volatile("ldmatrix.sync.aligned.m8n8.x4.shared.b16 {%0,%1,%2,%3}, [%4];"
        : "=r"(r[0]), "=r"(r[1]), "=r"(r[2]), "=r"(r[3]) : "r"(addr));
}
__device__ __forceinline__ void ldsm_x4_t(uint32_t* r, uint32_t addr) {
    asm volatile("ldmatrix.sync.aligned.m8n8.x4.trans.shared.b16 {%0,%1,%2,%3}, [%4];"
        : "=r"(r[0]), "=r"(r[1]), "=r"(r[2]), "=r"(r[3]) : "r"(addr));
}
__device__ __forceinline__ void mma_bf16(float* d, const uint32_t* a, const uint32_t* b) {
    asm volatile("mma.sync.aligned.m16n8k16.row.col.f32.bf16.bf16.f32 "
        "{%0,%1,%2,%3}, {%4,%5,%6,%7}, {%8,%9}, {%0,%1,%2,%3};"
        : "+f"(d[0]), "+f"(d[1]), "+f"(d[2]), "+f"(d[3])
        : "r"(a[0]), "r"(a[1]), "r"(a[2]), "r"(a[3]), "r"(b[0]), "r"(b[1]));
}

// swizzles: 64B-row tiles (GEMM, 32 bf16 cols) and 128B-row tiles (flash, 64 cols)
__device__ __forceinline__ uint32_t tswz(int r, int c)    { return (uint32_t)(r * 64  + ((c ^ ((r >> 1) & 3)) << 4)); }
__device__ __forceinline__ uint32_t tswz128(int r, int c) { return (uint32_t)(r * 128 + ((c ^ (r & 7)) << 4)); }

// truncation hi/lo bf16 pair packers (for P fragments)
__device__ __forceinline__ uint32_t bf16hi_pair(float a, float b) {
    return __byte_perm(__float_as_uint(a), __float_as_uint(b), 0x7632);
}
__device__ __forceinline__ uint32_t bf16lo_pair(float a, float b) {
    float la = a - __uint_as_float(__float_as_uint(a) & 0xFFFF0000u);
    float lb = b - __uint_as_float(__float_as_uint(b) & 0xFFFF0000u);
    uint32_t r;
    asm("cvt.rn.bf16x2.f32 %0, %1, %2;" : "=r"(r) : "f"(lb), "f"(la));
    return r;
}
// round hi/lo split + paired store
__device__ __forceinline__ void split_store2(__nv_bfloat16* Ph, __nv_bfloat16* Pl,
                                             size_t off, float a, float b) {
    __nv_bfloat16 ha = __float2bfloat16(a), hb = __float2bfloat16(b);
    *(__nv_bfloat162*)(Ph + off) = __halves2bfloat162(ha, hb);
    *(__nv_bfloat162*)(Pl + off) = __halves2bfloat162(
        __float2bfloat16(a - __bfloat162float(ha)),
        __float2bfloat16(b - __bfloat162float(hb)));
}

// ============================================================
// fp32 -> (hi, lo) bf16 split
// ============================================================
__global__ void split_kernel(const float* __restrict__ in, __nv_bfloat16* __restrict__ hi,
                             __nv_bfloat16* __restrict__ lo, int n)
{
    int i = blockIdx.x * blockDim.x + threadIdx.x;
    int stride = gridDim.x * blockDim.x;
    for (; i < n; i += stride) {
        float x = in[i];
        __nv_bfloat16 h = __float2bfloat16(x);
        hi[i] = h;
        lo[i] = __float2bfloat16(x - __bfloat162float(h));
    }
}

// W[K=1024, N] -> W^T hi/lo [N, 1024]
__global__ void tsplit_kernel(const float* __restrict__ in, __nv_bfloat16* __restrict__ hi,
                              __nv_bfloat16* __restrict__ lo, int N)
{
    __shared__ float s[32][33];
    const int n0 = blockIdx.x * 32, k0 = blockIdx.y * 32;
    const int tx = threadIdx.x, ty = threadIdx.y;
#pragma unroll
    for (int i = 0; i < 32; i += 8)
        s[ty + i][tx] = in[(size_t)(k0 + ty + i) * N + n0 + tx];
    __syncthreads();
#pragma unroll
    for (int i = 0; i < 32; i += 8) {
        float x = s[tx][ty + i];
        __nv_bfloat16 h = __float2bfloat16(x);
        size_t o = (size_t)(n0 + ty + i) * HID + k0 + tx;
        hi[o] = h;
        lo[o] = __float2bfloat16(x - __bfloat162float(h));
    }
}

// ============================================================
// HMMA GEMM (bf16x3 split): C = A[M,1024] @ (B^T[N,1024])^T
// 3-stage cp.async pipeline, ONE __syncthreads per BK=32 iter.
//   EPI 0: QKV -> bf16 hi/lo scatter into q/k/v (q scaled)
//   EPI 1: dense (+bias) -> fp32 out
// ============================================================
#define TILE_B8 8192
#define STAGE_B 32768
#define GEMM_SMEM (3 * STAGE_B)   // 96KB

__device__ __forceinline__ void load_stage(uint32_t sb,
    const __nv_bfloat16* __restrict__ Ah, const __nv_bfloat16* __restrict__ Al,
    const __nv_bfloat16* __restrict__ Bh, const __nv_bfloat16* __restrict__ Bl,
    int row0, int col0, int k0, int tid)
{
    const __nv_bfloat16* srcs[4] = { Ah, Al, Bh, Bl };
    const int bases[4] = { row0, row0, col0, col0 };
#pragma unroll
    for (int tI = 0; tI < 4; tI++) {
#pragma unroll
        for (int h = 0; h < 2; h++) {
            const int q = tid + h * 256;
            const int r = q >> 2, c = q & 3;
            cp16(sb + tI * TILE_B8 + tswz(r, c),
                 srcs[tI] + (size_t)(bases[tI] + r) * HID + k0 + c * 8);
        }
    }
}

template<int EPI>
__global__ void __launch_bounds__(256) gemm_mma(const __nv_bfloat16* __restrict__ Ah,
                                                const __nv_bfloat16* __restrict__ Al,
                                                const __nv_bfloat16* __restrict__ Bh,
                                                const __nv_bfloat16* __restrict__ Bl,
                                                const float* __restrict__ bias,
                                                float* __restrict__ out)
{
    extern __shared__ char sm[];
    const uint32_t smb = smem_u32(sm);
    const int tid  = threadIdx.x;
    const int lane = tid & 31;
    const int wid  = tid >> 5;
    const int wm   = wid >> 1;
    const int wn   = wid & 1;
    const int row0 = blockIdx.y * 128;
    const int col0 = blockIdx.x * 128;

    float acc[2][8][4];
#pragma unroll
    for (int i = 0; i < 2; i++)
#pragma unroll
        for (int j = 0; j < 8; j++)
#pragma unroll
            for (int e = 0; e < 4; e++) acc[i][j][e] = 0.0f;

    const int arow = (lane & 15);
    const int akch = lane >> 4;
    const int brow = (lane & 7) + ((lane >> 4) << 3);
    const int bkch = (lane >> 3) & 1;

    // prologue: fill stages 0 and 1
    load_stage(smb + 0 * STAGE_B, Ah, Al, Bh, Bl, row0, col0, 0, tid);
    CP_COMMIT();
    load_stage(smb + 1 * STAGE_B, Ah, Al, Bh, Bl, row0, col0, 32, tid);
    CP_COMMIT();

    for (int ks = 0; ks < 32; ks++) {
        if (ks == 31) { CP_WAIT(0); } else { CP_WAIT(1); }
        __syncthreads();
        const uint32_t sb = smb + (uint32_t)(ks % 3) * STAGE_B;

#pragma unroll
        for (int s = 0; s < 2; s++) {
            uint32_t afh[2][4], afl[2][4];
#pragma unroll
            for (int mt = 0; mt < 2; mt++) {
                const int r = wm * 32 + mt * 16 + arow;
                const int c = s * 2 + akch;
                ldsm_x4(afh[mt], sb + 0 * TILE_B8 + tswz(r, c));
                ldsm_x4(afl[mt], sb + 1 * TILE_B8 + tswz(r, c));
            }
#pragma unroll
            for (int h = 0; h < 2; h++) {
                uint32_t bfh[2][4], bfl[2][4];
#pragma unroll
                for (int nt2 = 0; nt2 < 2; nt2++) {
                    const int r = wn * 64 + h * 32 + nt2 * 16 + brow;
                    const int c = s * 2 + bkch;
                    ldsm_x4(bfh[nt2], sb + 2 * TILE_B8 + tswz(r, c));
                    ldsm_x4(bfl[nt2], sb + 3 * TILE_B8 + tswz(r, c));
                }
#pragma unroll
                for (int mt = 0; mt < 2; mt++)
#pragma unroll
                    for (int n8 = 0; n8 < 4; n8++) {
                        float* d = acc[mt][h * 4 + n8];
                        const uint32_t* ph = &bfh[n8 >> 1][(n8 & 1) * 2];
                        const uint32_t* pl = &bfl[n8 >> 1][(n8 & 1) * 2];
                        mma_bf16(d, afh[mt], ph);
                        mma_bf16(d, afh[mt], pl);
                        mma_bf16(d, afl[mt], ph);
                    }
            }
        }

        // refill the slot freed at iter ks-1 (barrier above guarantees safety)
        if (ks + 2 < 32) {
            load_stage(smb + (uint32_t)((ks + 2) % 3) * STAGE_B,
                       Ah, Al, Bh, Bl, row0, col0, (ks + 2) * 32, tid);
            CP_COMMIT();
        }
    }

    // epilogue
    const int gm  = lane >> 2;
    const int gn2 = (lane & 3) * 2;
#pragma unroll
    for (int mt = 0; mt < 2; mt++) {
#pragma unroll
        for (int j = 0; j < 8; j++) {
            const int col = col0 + wn * 64 + j * 8 + gn2;
            const float b0 = bias[col], b1 = bias[col + 1];
            const int rlo = row0 + wm * 32 + mt * 16 + gm;
            const int rhi = rlo + 8;
            float v00 = acc[mt][j][0] + b0, v01 = acc[mt][j][1] + b1;
            float v10 = acc[mt][j][2] + b0, v11 = acc[mt][j][3] + b1;
            if (EPI == 0) {
                const int chunk = col >> 10;
                const int cc = col & 1023;
                const int hh = cc >> 6;
                const int dd = cc & 63;
                __nv_bfloat16 *dh, *dl;
                if (chunk == 0)      { dh = g_kh; dl = g_kl; }
                else if (chunk == 1) { dh = g_vh; dl = g_vl; }
                else { dh = g_qh; dl = g_ql;
                       v00 *= QSCALE; v01 *= QSCALE; v10 *= QSCALE; v11 *= QSCALE; }
                {
                    const int b_ = rlo >> 11, s_ = rlo & 2047;
                    split_store2(dh, dl, ((size_t)(b_ * NHEAD + hh) * SLEN + s_) * HDIM + dd, v00, v01);
                }
                {
                    const int b_ = rhi >> 11, s_ = rhi & 2047;
                    split_store2(dh, dl, ((size_t)(b_ * NHEAD + hh) * SLEN + s_) * HDIM + dd, v10, v11);
                }
            } else {
                *(float2*)(out + (size_t)rlo * HID + col) = make_float2(v00, v01);
                *(float2*)(out + (size_t)rhi * HID + col) = make_float2(v10, v11);
            }
        }
    }
}

// ============================================================
// Flash attention, HMMA bf16x3, causal. BQ=128, BK=64.
// 3-stage KV pipeline, ONE __syncthreads per k-tile.
// grid = (16, NHEAD, BATCH), 256 threads (8 warps x 16 q-rows)
// smem: Qh|Ql (32KB) + 3 stages x (Kh|Kl|Vh|Vl) (96KB) = 128KB
// ============================================================
#define FKV_BASE  32768
#define FKV_STAGE 32768
#define FLASH_SMEM (FKV_BASE + 3 * FKV_STAGE)   // 131072

__device__ __forceinline__ void load_kv_stage(uint32_t sb,
    const __nv_bfloat16* __restrict__ Kh, const __nv_bfloat16* __restrict__ Kl,
    const __nv_bfloat16* __restrict__ Vh, const __nv_bfloat16* __restrict__ Vl,
    int k0, int tid)
{
    const __nv_bfloat16* srcs[4] = { Kh, Kl, Vh, Vl };
#pragma unroll
    for (int t = 0; t < 4; t++) {
#pragma unroll
        for (int hh = 0; hh < 2; hh++) {
            const int r = (tid >> 3) + hh * 32;
            const int c = tid & 7;
            cp16(sb + t * 8192 + tswz128(r, c), srcs[t] + (size_t)(k0 + r) * HDIM + c * 8);
        }
    }
}

__global__ void __launch_bounds__(256) flash_mma()
{
    extern __shared__ char sm[];
    const uint32_t smb = smem_u32(sm);
    const int tid = threadIdx.x, lane = tid & 31, wid = tid >> 5;
    const int qt = blockIdx.x, h = blockIdx.y, b = blockIdx.z;
    const int q0 = qt * 128;
    const size_t bh = ((size_t)(b * NHEAD + h)) * SLEN * HDIM;
    const __nv_bfloat16 *Qh = g_qh + bh, *Ql = g_ql + bh;
    const __nv_bfloat16 *Kh = g_kh + bh, *Kl = g_kl + bh;
    const __nv_bfloat16 *Vh = g_vh + bh, *Vl = g_vl + bh;
    const int nk = 2 * qt + 2;

    // prologue: Q + kv stage0 (group 0), kv stage1 (group 1)
#pragma unroll
    for (int t = 0; t < 2; t++) {
#pragma unroll
        for (int hh = 0; hh < 4; hh++) {
            const int r = (tid >> 3) + hh * 32;
            const int c = tid & 7;
            cp16(smb + t * 16384 + tswz128(r, c),
                 (t ? Ql : Qh) + (size_t)(q0 + r) * HDIM + c * 8);
        }
    }
    load_kv_stage(smb + FKV_BASE, Kh, Kl, Vh, Vl, 0, tid);
    CP_COMMIT();
    load_kv_stage(smb + FKV_BASE + FKV_STAGE, Kh, Kl, Vh, Vl, 64, tid);
    CP_COMMIT();
    CP_WAIT(1);
    __syncthreads();

    // Q fragments, register-resident (Q smem never overwritten)
    uint32_t qfh[4][4], qfl[4][4];
    {
        const int arow = 16 * wid + (lane & 15);
        const int ach  = lane >> 4;
#pragma unroll
        for (int s = 0; s < 4; s++) {
            ldsm_x4(qfh[s], smb + tswz128(arow, s * 2 + ach));
            ldsm_x4(qfl[s], smb + 16384 + tswz128(arow, s * 2 + ach));
        }
    }

    float O[8][4];
#pragma unroll
    for (int j = 0; j < 8; j++)
#pragma unroll
        for (int e = 0; e < 4; e++) O[j][e] = 0.0f;
    float m0 = -1e30f, m1 = -1e30f, l0 = 0.0f, l1 = 0.0f;

    const int brow = (lane & 7) + ((lane >> 4) << 3);
    const int bkch = (lane >> 3) & 1;
    const int vrow = lane & 15;
    const int vch  = lane >> 4;
    const int rg0  = q0 + 16 * wid + (lane >> 2);

    for (int t = 0; t < nk; t++) {
        if (t > 0) {
            if (t == nk - 1) { CP_WAIT(0); } else { CP_WAIT(1); }
            __syncthreads();
        }
        const uint32_t sb = smb + FKV_BASE + (uint32_t)(t % 3) * FKV_STAGE;
        const int k0 = t * 64;

        // ---- S = Q K^T (3-term) ----
        float s_[8][4];
#pragma unroll
        for (int j = 0; j < 8; j++)
#pragma unroll
            for (int e = 0; e < 4; e++) s_[j][e] = 0.0f;

#pragma unroll
        for (int s = 0; s < 4; s++) {
#pragma unroll
            for (int jj = 0; jj < 4; jj++) {
                uint32_t kfh[4], kfl[4];
                ldsm_x4(kfh, sb + tswz128(jj * 16 + brow, s * 2 + bkch));
                ldsm_x4(kfl, sb + 8192 + tswz128(jj * 16 + brow, s * 2 + bkch));
                mma_bf16(s_[2 * jj],     qfh[s], kfh + 0);
                mma_bf16(s_[2 * jj],     qfh[s], kfl + 0);
                mma_bf16(s_[2 * jj],     qfl[s], kfh + 0);
                mma_bf16(s_[2 * jj + 1], qfh[s], kfh + 2);
                mma_bf16(s_[2 * jj + 1], qfh[s], kfl + 2);
                mma_bf16(s_[2 * jj + 1], qfl[s], kfh + 2);
            }
        }

        // ---- causal mask (diagonal region only) ----
        if (k0 + 63 > q0 + 16 * wid) {
#pragma unroll
            for (int j = 0; j < 8; j++) {
                const int col = k0 + j * 8 + 2 * (lane & 3);
                if (col     > rg0)     s_[j][0] = MASKB;
                if (col + 1 > rg0)     s_[j][1] = MASKB;
                if (col     > rg0 + 8) s_[j][2] = MASKB;
                if (col + 1 > rg0 + 8) s_[j][3] = MASKB;
            }
        }

        // ---- online softmax ----
        float mx0 = s_[0][0], mx1 = s_[0][2];
#pragma unroll
        for (int j = 0; j < 8; j++) {
            mx0 = fmaxf(mx0, fmaxf(s_[j][0], s_[j][1]));
            mx1 = fmaxf(mx1, fmaxf(s_[j][2], s_[j][3]));
        }
        mx0 = fmaxf(mx0, __shfl_xor_sync(0xffffffffu, mx0, 1));
        mx0 = fmaxf(mx0, __shfl_xor_sync(0xffffffffu, mx0, 2));
        mx1 = fmaxf(mx1, __shfl_xor_sync(0xffffffffu, mx1, 1));
        mx1 = fmaxf(mx1, __shfl_xor_sync(0xffffffffu, mx1, 2));
        const float mn0 = fmaxf(m0, mx0), mn1 = fmaxf(m1, mx1);
        const float c0 = __expf(m0 - mn0), c1 = __expf(m1 - mn1);
        m0 = mn0; m1 = mn1;
        float rs0 = 0.0f, rs1 = 0.0f;
#pragma unroll
        for (int j = 0; j < 8; j++) {
            s_[j][0] = __expf(s_[j][0] - mn0);
            s_[j][1] = __expf(s_[j][1] - mn0);
            s_[j][2] = __expf(s_[j][2] - mn1);
            s_[j][3] = __expf(s_[j][3] - mn1);
            rs0 += s_[j][0] + s_[j][1];
            rs1 += s_[j][2] + s_[j][3];
            O[j][0] *= c0; O[j][1] *= c0; O[j][2] *= c1; O[j][3] *= c1;
        }
        rs0 += __shfl_xor_sync(0xffffffffu, rs0, 1);
        rs0 += __shfl_xor_sync(0xffffffffu, rs0, 2);
        rs1 += __shfl_xor_sync(0xffffffffu, rs1, 1);
        rs1 += __shfl_xor_sync(0xffffffffu, rs1, 2);
        l0 = l0 * c0 + rs0;
        l1 = l1 * c1 + rs1;

        // ---- P fragments (truncation hi/lo split) ----
        uint32_t pah[4][4], pal[4][4];
#pragma unroll
        for (int kk = 0; kk < 4; kk++) {
            const int j0 = 2 * kk, j1 = 2 * kk + 1;
            pah[kk][0] = bf16hi_pair(s_[j0][0], s_[j0][1]);
            pah[kk][1] = bf16hi_pair(s_[j0][2], s_[j0][3]);
            pah[kk][2] = bf16hi_pair(s_[j1][0], s_[j1][1]);
            pah[kk][3] = bf16hi_pair(s_[j1][2], s_[j1][3]);
            pal[kk][0] = bf16lo_pair(s_[j0][0], s_[j0][1]);
            pal[kk][1] = bf16lo_pair(s_[j0][2], s_[j0][3]);
            pal[kk][2] = bf16lo_pair(s_[j1][0], s_[j1][1]);
            pal[kk][3] = bf16lo_pair(s_[j1][2], s_[j1][3]);
        }

        // ---- O += P V (3-term) ----
#pragma unroll
        for (int kk = 0; kk < 4; kk++) {
#pragma unroll
            for (int dd = 0; dd < 4; dd++) {
                uint32_t vfh[4], vfl[4];
                ldsm_x4_t(vfh, sb + 16384 + tswz128(kk * 16 + vrow, 2 * dd + vch));
                ldsm_x4_t(vfl, sb + 24576 + tswz128(kk * 16 + vrow, 2 * dd + vch));
                mma_bf16(O[2 * dd],     pah[kk], vfh + 0);
                mma_bf16(O[2 * dd],     pah[kk], vfl + 0);
                mma_bf16(O[2 * dd],     pal[kk], vfh + 0);
                mma_bf16(O[2 * dd + 1], pah[kk], vfh + 2);
                mma_bf16(O[2 * dd + 1], pah[kk], vfl + 2);
                mma_bf16(O[2 * dd + 1], pal[kk], vfh + 2);
            }
        }

        // refill slot freed at iter t-1 (barrier at top of iter t made it safe)
        if (t + 2 < nk) {
            load_kv_stage(smb + FKV_BASE + (uint32_t)((t + 2) % 3) * FKV_STAGE,
                          Kh, Kl, Vh, Vl, (t + 2) * 64, tid);
            CP_COMMIT();
        }
    }

    // ---- write ctx hi/lo ----
    const float inv0 = 1.0f / l0, inv1 = 1.0f / l1;
    const int r0 = q0 + 16 * wid + (lane >> 2);
    const int r1 = r0 + 8;
    const size_t base0 = ((size_t)b * SLEN + r0) * HID + h * HDIM + 2 * (lane & 3);
    const size_t base1 = ((size_t)b * SLEN + r1) * HID + h * HDIM + 2 * (lane & 3);
#pragma unroll
    for (int j = 0; j < 8; j++) {
        split_store2(g_Ch, g_Cl, base0 + j * 8, O[j][0] * inv0, O[j][1] * inv0);
        split_store2(g_Ch, g_Cl, base1 + j * 8, O[j][2] * inv1, O[j][3] * inv1);
    }
}

// ============================================================
// launch
// ============================================================
extern "C" void kernel_launch(void* const* d_in, const int* in_sizes, int n_in,
                              void* d_out, int out_size)
{
    const float* hs      = (const float*)d_in[0];
    const float* w_qkv   = (const float*)d_in[1];
    const float* b_qkv   = (const float*)d_in[2];
    const float* w_dense = (const float*)d_in[3];
    const float* b_dense = (const float*)d_in[4];
    float* out = (float*)d_out;

    __nv_bfloat16 *Ah, *Al, *Ch, *Cl, *Wqh, *Wql, *Wdh, *Wdl;
    cudaGetSymbolAddress((void**)&Ah,  g_Ah);
    cudaGetSymbolAddress((void**)&Al,  g_Al);
    cudaGetSymbolAddress((void**)&Ch,  g_Ch);
    cudaGetSymbolAddress((void**)&Cl,  g_Cl);
    cudaGetSymbolAddress((void**)&Wqh, g_Wqh);
    cudaGetSymbolAddress((void**)&Wql, g_Wql);
    cudaGetSymbolAddress((void**)&Wdh, g_Wdh);
    cudaGetSymbolAddress((void**)&Wdl, g_Wdl);

    cudaFuncSetAttribute(flash_mma, cudaFuncAttributeMaxDynamicSharedMemorySize, FLASH_SMEM);
    cudaFuncSetAttribute(gemm_mma<0>, cudaFuncAttributeMaxDynamicSharedMemorySize, GEMM_SMEM);
    cudaFuncSetAttribute(gemm_mma<1>, cudaFuncAttributeMaxDynamicSharedMemorySize, GEMM_SMEM);

    // 1. split inputs
    split_kernel<<<2048, 256>>>(hs, Ah, Al, ROWS * HID);
    tsplit_kernel<<<dim3(NQKV / 32, HID / 32), dim3(32, 8)>>>(w_qkv, Wqh, Wql, NQKV);
    tsplit_kernel<<<dim3(HID / 32, HID / 32), dim3(32, 8)>>>(w_dense, Wdh, Wdl, HID);

    // 2. QKV GEMM -> bf16 hi/lo q/k/v
    dim3 gq(NQKV / 128, ROWS / 128);
    gemm_mma<0><<<gq, 256, GEMM_SMEM>>>(Ah, Al, Wqh, Wql, b_qkv, nullptr);

    // 3. flash attention (HMMA) -> ctx hi/lo
    dim3 gf(SLEN / 128, NHEAD, BATCH);
    flash_mma<<<gf, 256, FLASH_SMEM>>>();

    // 4. dense GEMM -> out
    dim3 gd(HID / 128, ROWS / 128);
    gemm_mma<1><<<gd, 256, GEMM_SMEM>>>(Ch, Cl, Wdh, Wdl, b_dense, out);
}